// round 2
// baseline (speedup 1.0000x reference)
#include <cuda_runtime.h>
#include <cstdint>

// RVQ: B=32, T=4096, MEL=128, D=64, K=128. N = 131072 tokens.
// recon = dec0[i0] + dec1[i1]; i0/i1 from fused scores GEMM + Gram fold.

#define NTOK   (32 * 4096)
#define NTILE  (NTOK / 64)
#define NTHR   256

// ---- precomputed tables (device globals; allocation-free scratch) ----
__device__ __align__(16) float g_twoG[128 * 128]; // 2 * cb0[j] . cb1[k]
__device__ __align__(16) float g_dec0[128 * 128]; // cb0[j] @ w_out^T + b_out
__device__ __align__(16) float g_dec1[128 * 128]; // cb1[j] @ w_out^T
__device__ __align__(16) float g_cT[64 * 256];    // cT[d][k]: k<128 -> cb0[k][d], else cb1[k-128][d]
__device__ __align__(16) float g_wT[128 * 64];    // wT[m][d] = w_in[d][m]
__device__ __align__(16) float g_c0n[128];
__device__ __align__(16) float g_c1n[128];

__device__ __forceinline__ float dot64(const float* __restrict__ a,
                                       const float* __restrict__ b) {
    float s = 0.f;
    const float4* b4 = (const float4*)b;
#pragma unroll
    for (int q = 0; q < 16; ++q) {
        float4 v = b4[q];
        s += a[4*q+0]*v.x + a[4*q+1]*v.y + a[4*q+2]*v.z + a[4*q+3]*v.w;
    }
    return s;
}

__global__ void rvq_precompute(const float* __restrict__ w_in,
                               const float* __restrict__ cb0,
                               const float* __restrict__ cb1,
                               const float* __restrict__ w_out,
                               const float* __restrict__ b_out) {
    __shared__ float c0r[64], c1r[64];
    const int j = blockIdx.x;      // 0..127
    const int t = threadIdx.x;     // 0..255
    if (t < 64)        c0r[t]      = cb0[j * 64 + t];
    else if (t < 128)  c1r[t - 64] = cb1[j * 64 + (t - 64)];
    __syncthreads();

    if (t < 128) {
        g_twoG[j * 128 + t] = 2.f * dot64(c0r, cb1 + t * 64);
        g_dec1[j * 128 + t] = dot64(c1r, w_out + t * 64);
        if (j < 64) {                       // wT: 8192 elems over 64 blocks
            int e = j * 128 + t;            // e = m*64 + d
            g_wT[e] = w_in[(e & 63) * 128 + (e >> 6)];
        }
    } else {
        int m = t - 128;
        g_dec0[j * 128 + m] = dot64(c0r, w_out + m * 64) + b_out[m];
        int e = j * 128 + m;                // cT: e = d*256 + k
        int d = e >> 8, k = e & 255;
        g_cT[e] = (k < 128) ? cb0[k * 64 + d] : cb1[(k - 128) * 64 + d];
    }
    if (t == 0)  { float s = 0.f; for (int d = 0; d < 64; ++d) s += c0r[d]*c0r[d]; g_c0n[j] = s; }
    if (t == 32) { float s = 0.f; for (int d = 0; d < 64; ++d) s += c1r[d]*c1r[d]; g_c1n[j] = s; }
}

// ---- smem layout (floats) ----
// region A [0,16640): phase1 = mel[64][132] (8448) + wT chunks [128][64] (8192)
//                     phase2 = cT[64][256] (16384, XOR-swizzled chunks)
// Z  [16640,20992): z[64][68]
// pv [20992,21248)  pk(int) [21248,21504)  i0s [21504,21568)  i1s [21568,21632)
#define OFF_W   8448
#define OFF_Z   16640
#define OFF_PV  20992
#define OFF_PK  21248
#define OFF_I0  21504
#define OFF_I1  21568
#define SMEM_FLOATS 21632
#define SMEM_BYTES  (SMEM_FLOATS * 4)

__global__ void __launch_bounds__(NTHR, 2)
rvq_main(const float* __restrict__ mel, const float* __restrict__ b_in,
         float* __restrict__ out) {
    extern __shared__ float sm[];
    float* smMel = sm;                 // stride 132
    float4* smW4 = (float4*)(sm + OFF_W);   // [m][16] chunks
    float4* smC4 = (float4*)sm;             // [d][64] chunks, swizzled
    float* smZ   = sm + OFF_Z;              // stride 68
    float* pv    = sm + OFF_PV;
    int*   pk    = (int*)(sm + OFF_PK);
    int*   i0s   = (int*)(sm + OFF_I0);
    int*   i1s   = (int*)(sm + OFF_I1);

    const int tid  = threadIdx.x;
    const int tile = blockIdx.x;
    const int kq8  = tid & 7;          // 0..7
    const int t0   = (tid >> 3) * 2;   // token pair base 0..62

    // ---- stage mel (64x128) + wT ----
    {
        const float4* mg = (const float4*)(mel + (size_t)tile * (64 * 128));
#pragma unroll
        for (int r = 0; r < 8; ++r) {
            int f = tid + NTHR * r;            // 0..2047 float4
            int tk = f >> 5, m4 = f & 31;
            *(float4*)(smMel + tk * 132 + m4 * 4) = mg[f];
        }
        const float4* wg = (const float4*)g_wT;
#pragma unroll
        for (int r = 0; r < 8; ++r) { int f = tid + NTHR * r; smW4[f] = wg[f]; }
    }
    __syncthreads();

    // ---- phase 1: z = mel @ w_in^T + b_in. 2 tok x 8 d (d = kq8*4 + 32j + q)
    {
        float acc[2][2][4];
        const float4* b4 = (const float4*)b_in;
        float4 bj0 = b4[kq8], bj1 = b4[8 + kq8];
#pragma unroll
        for (int i = 0; i < 2; ++i) {
            acc[i][0][0]=bj0.x; acc[i][0][1]=bj0.y; acc[i][0][2]=bj0.z; acc[i][0][3]=bj0.w;
            acc[i][1][0]=bj1.x; acc[i][1][1]=bj1.y; acc[i][1][2]=bj1.z; acc[i][1][3]=bj1.w;
        }
        const float* m0 = smMel + t0 * 132;
        const float* m1 = smMel + (t0 + 1) * 132;
#pragma unroll 4
        for (int m = 0; m < 128; ++m) {
            float a0 = m0[m], a1 = m1[m];
            float4 w0 = smW4[m * 16 + kq8];
            float4 w1 = smW4[m * 16 + 8 + kq8];
            acc[0][0][0] += a0*w0.x; acc[0][0][1] += a0*w0.y; acc[0][0][2] += a0*w0.z; acc[0][0][3] += a0*w0.w;
            acc[0][1][0] += a0*w1.x; acc[0][1][1] += a0*w1.y; acc[0][1][2] += a0*w1.z; acc[0][1][3] += a0*w1.w;
            acc[1][0][0] += a1*w0.x; acc[1][0][1] += a1*w0.y; acc[1][0][2] += a1*w0.z; acc[1][0][3] += a1*w0.w;
            acc[1][1][0] += a1*w1.x; acc[1][1][1] += a1*w1.y; acc[1][1][2] += a1*w1.z; acc[1][1][3] += a1*w1.w;
        }
#pragma unroll
        for (int i = 0; i < 2; ++i)
#pragma unroll
            for (int j = 0; j < 2; ++j)
                *(float4*)(smZ + (t0 + i) * 68 + kq8 * 4 + 32 * j) =
                    make_float4(acc[i][j][0], acc[i][j][1], acc[i][j][2], acc[i][j][3]);
    }
    __syncthreads();  // z done; region A free

    // ---- stage cT with XOR chunk swizzle (chunk c -> c ^ ((c>>3)&7)) ----
    {
        const float4* cg = (const float4*)g_cT;
#pragma unroll
        for (int r = 0; r < 16; ++r) {
            int f = tid + NTHR * r;            // 0..4095 float4
            int d = f >> 6, c = f & 63;
            smC4[d * 64 + (c ^ ((c >> 3) & 7))] = cg[f];
        }
    }
    __syncthreads();

    // ---- phase 2: scores s[tok][k] = z . cT, 2 tok x 32 k (k = kq8*32 + 4j + q)
    float s[2][32];
#pragma unroll
    for (int i = 0; i < 2; ++i)
#pragma unroll
        for (int kk = 0; kk < 32; ++kk) s[i][kk] = 0.f;

    {
        const float* z0p = smZ + t0 * 68;
        const float* z1p = smZ + (t0 + 1) * 68;
#pragma unroll 2
        for (int d = 0; d < 64; ++d) {
            float z0 = z0p[d], z1 = z1p[d];
            const float4* crow = smC4 + d * 64 + kq8 * 8;
#pragma unroll
            for (int j = 0; j < 8; ++j) {
                float4 c = crow[j ^ kq8];      // logical chunk kq8*8+j
                s[0][4*j+0] += z0*c.x; s[0][4*j+1] += z0*c.y;
                s[0][4*j+2] += z0*c.z; s[0][4*j+3] += z0*c.w;
                s[1][4*j+0] += z1*c.x; s[1][4*j+1] += z1*c.y;
                s[1][4*j+2] += z1*c.z; s[1][4*j+3] += z1*c.w;
            }
        }
    }

    // ---- level-0 argmin (k in [0,128): kq8 < 4) ----
    if (kq8 < 4) {
#pragma unroll
        for (int i = 0; i < 2; ++i) {
            float best = 3.402823466e38f; int bi = 0;
#pragma unroll
            for (int kk = 0; kk < 32; ++kk) {
                int k = kq8 * 32 + kk;
                float v = g_c0n[k] - 2.f * s[i][kk];
                if (v < best) { best = v; bi = k; }
            }
            pv[(t0 + i) * 4 + kq8] = best;
            pk[(t0 + i) * 4 + kq8] = bi;
        }
    }
    __syncthreads();
    if (tid < 64) {
        float best = pv[tid * 4]; int bi = pk[tid * 4];
#pragma unroll
        for (int q = 1; q < 4; ++q) {
            float v = pv[tid * 4 + q];
            if (v < best) { best = v; bi = pk[tid * 4 + q]; }
        }
        i0s[tid] = bi;
    }
    __syncthreads();

    // ---- level-1 argmin (k1 in [0,128): kq8 >= 4) with Gram fold ----
    if (kq8 >= 4) {
#pragma unroll
        for (int i = 0; i < 2; ++i) {
            const float* grow = g_twoG + i0s[t0 + i] * 128;
            float best = 3.402823466e38f; int bi = 0;
#pragma unroll
            for (int kk = 0; kk < 32; ++kk) {
                int k1 = (kq8 - 4) * 32 + kk;
                float v = g_c1n[k1] - 2.f * s[i][kk] + grow[k1];
                if (v < best) { best = v; bi = k1; }
            }
            pv[(t0 + i) * 4 + (kq8 - 4)] = best;
            pk[(t0 + i) * 4 + (kq8 - 4)] = bi;
        }
    }
    __syncthreads();
    if (tid < 64) {
        float best = pv[tid * 4]; int bi = pk[tid * 4];
#pragma unroll
        for (int q = 1; q < 4; ++q) {
            float v = pv[tid * 4 + q];
            if (v < best) { best = v; bi = pk[tid * 4 + q]; }
        }
        i1s[tid] = bi;
    }
    __syncthreads();

    // ---- phase 3: out = dec0[i0] + dec1[i1] (coalesced float4) ----
    {
        const float4* d0 = (const float4*)g_dec0;
        const float4* d1 = (const float4*)g_dec1;
        float4* o4 = (float4*)out + (size_t)tile * 2048;
#pragma unroll
        for (int r = 0; r < 8; ++r) {
            int f = tid + NTHR * r;            // 0..2047
            int tok = f >> 5, m4 = f & 31;
            float4 a = d0[i0s[tok] * 32 + m4];
            float4 b = d1[i1s[tok] * 32 + m4];
            o4[f] = make_float4(a.x + b.x, a.y + b.y, a.z + b.z, a.w + b.w);
        }
    }
}

extern "C" void kernel_launch(void* const* d_in, const int* in_sizes, int n_in,
                              void* d_out, int out_size) {
    const float* mel   = (const float*)d_in[0];
    const float* w_in  = (const float*)d_in[1];
    const float* b_in  = (const float*)d_in[2];
    const float* cb0   = (const float*)d_in[3];
    const float* cb1   = (const float*)d_in[4];
    const float* w_out = (const float*)d_in[5];
    const float* b_out = (const float*)d_in[6];
    float* out = (float*)d_out;

    cudaFuncSetAttribute(rvq_main, cudaFuncAttributeMaxDynamicSharedMemorySize, SMEM_BYTES);

    rvq_precompute<<<128, NTHR>>>(w_in, cb0, cb1, w_out, b_out);
    rvq_main<<<NTILE, NTHR, SMEM_BYTES>>>(mel, b_in, out);
}